// round 10
// baseline (speedup 1.0000x reference)
#include <cuda_runtime.h>

#define HID 1024
#define NSAMP 1024
#define TSTEPS 98
#define G 8            // samples per CTA
#define NTHR 256       // threads per CTA
#define NCTA (NSAMP / G)

// dynamic smem layout (bytes)
#define SM_TBL   0        // 256 masks x 4 ulonglong2 = 16384
#define SM_DC    16384    // G*NTHR ulonglong2 = 32768
#define SM_LISTA 49152    // 4096
#define SM_LISTB 53248    // 4096
#define SM_WARP  57344    // 32
#define SM_XSH   57376    // 256
#define SM_RED   57632    // 128
#define SM_TOTAL 57760

__device__ float g_W2J[HID * HID];  // [src h][reordered dest col]
__device__ float g_W3J[HID * HID];
__device__ int g_u2[HID];           // col -> dest unit (layer 2 ordering)
__device__ int g_u3[HID];           // col -> dest unit (layer 3 ordering)
__device__ int g_S2[99];            // group prefix sums (98 groups)
__device__ int g_S3[2][50];         // per-parity group prefix sums
__device__ float g_fr[3];

// ---------------------------------------------------------------------------
__global__ void init_tables() {
    if (threadIdx.x != 0 || blockIdx.x != 0) return;
    int s = 0;
    for (int g = 0; g < 98; g++) {
        g_S2[g] = s;
        int rho = (3 * g) % 98;
        int cnt = (rho < 44) ? 11 : 10;
        for (int i = 0; i < cnt; i++) g_u2[s + i] = rho + 98 * i;
        s += cnt;
    }
    g_S2[98] = s;
    for (int p = 0; p < 2; p++) {
        int sp = 512 * p;
        for (int g3 = 0; g3 < 49; g3++) {
            g_S3[p][g3] = sp;
            int q = (2 * g3) % 49;
            int rho = 2 * q + p;
            int cnt = (rho < 44) ? 11 : 10;
            for (int i = 0; i < cnt; i++) g_u3[sp + i] = rho + 98 * i;
            sp += cnt;
        }
        g_S3[p][49] = sp;
    }
    g_fr[0] = 0.0f; g_fr[1] = 0.0f; g_fr[2] = 0.0f;
}

// ---------------------------------------------------------------------------
__global__ void prep_kernel(const float* __restrict__ W2,
                            const float* __restrict__ W3) {
    __shared__ float tile[32][33];
    __shared__ int uu[32];
    const float* src = (blockIdx.z == 0) ? W2 : W3;
    float* dst = (blockIdx.z == 0) ? g_W2J : g_W3J;
    const int* umap = (blockIdx.z == 0) ? g_u2 : g_u3;
    int c0 = blockIdx.x * 32, h0 = blockIdx.y * 32;
    int tx = threadIdx.x, ty = threadIdx.y;
    if (ty == 0) uu[tx] = umap[c0 + tx];
    __syncthreads();
    tile[ty][tx] = src[uu[ty] * HID + h0 + tx];
    __syncthreads();
    dst[(h0 + ty) * HID + c0 + tx] = tile[tx][ty];
}

// ---------------------------------------------------------------------------
static __device__ __forceinline__ unsigned spread4(unsigned m) {
    return ((m & 0xFu) * 0x00204081u) & 0x01010101u;
}

static __device__ __forceinline__ unsigned bytesum(unsigned v, unsigned c) {
    unsigned ones = 0x01010101u;
    unsigned r;
    asm("dp4a.u32.u32 %0, %1, %2, %3;" : "=r"(r) : "r"(v), "r"(ones), "r"(c));
    return r;
}

// packed fma: d = b*w + d  elementwise on f32x2
#define FF2(d, b, w) \
    asm("fma.rn.f32x2 %0, %1, %2, %0;" : "+l"(d) : "l"(b), "l"(w))

// exclusive scan over 256 threads (8 warps)
static __device__ __forceinline__ void block_scan(int v, int tid, int* s_warp,
                                                  int& excl, int& total) {
    int lane = tid & 31, wid = tid >> 5;
    int x = v;
#pragma unroll
    for (int o = 1; o < 32; o <<= 1) {
        int y = __shfl_up_sync(0xffffffffu, x, o);
        if (lane >= o) x += y;
    }
    __syncthreads();
    if (lane == 31) s_warp[wid] = x;
    __syncthreads();
    int pre = 0, tot = 0;
#pragma unroll
    for (int w = 0; w < 8; w++) {
        int sw = s_warp[w];
        pre += (w < wid) ? sw : 0;
        tot += sw;
    }
    excl = pre + x - v;
    total = tot;
}

union F2U { unsigned long long u; float2 f; };

// one row's 8 FFMA2 per active pair (table entries tA..tD = dup bit floats)
#define ROW_FF(tA, tB, tC, tD, v1, v2)                                   \
    do {                                                                 \
        if (a1) {                                                        \
            FF2(acc1[0], (tA).x, (v1)); FF2(acc1[1], (tA).y, (v1));      \
            FF2(acc1[2], (tB).x, (v1)); FF2(acc1[3], (tB).y, (v1));      \
            FF2(acc1[4], (tC).x, (v1)); FF2(acc1[5], (tC).y, (v1));      \
            FF2(acc1[6], (tD).x, (v1)); FF2(acc1[7], (tD).y, (v1));      \
        }                                                                \
        if (a2) {                                                        \
            FF2(acc2[0], (tA).x, (v2)); FF2(acc2[1], (tA).y, (v2));      \
            FF2(acc2[2], (tB).x, (v2)); FF2(acc2[3], (tB).y, (v2));      \
            FF2(acc2[4], (tC).x, (v2)); FF2(acc2[5], (tC).y, (v2));      \
            FF2(acc2[6], (tD).x, (v2)); FF2(acc2[7], (tD).y, (v2));      \
        }                                                                \
    } while (0)

// union-row gather: pair1 cols (2tid,2tid+1) via pA, pair2 (+512) via pB.
// a1/a2: warp-uniform region-active flags. Weights depth-4, table depth-1.
static __device__ __forceinline__ void gatherP(
    const unsigned* __restrict__ list, int cnt,
    const unsigned long long* __restrict__ pA,
    const unsigned long long* __restrict__ pB,
    const ulonglong2* __restrict__ tbl, bool a1, bool a2,
    unsigned long long* acc1, unsigned long long* acc2) {
    if (cnt <= 0 || !(a1 || a2)) return;
    const int nb = cnt >> 2;
    if (nb > 0) {
        uint4 c = *reinterpret_cast<const uint4*>(list);
        unsigned e0 = c.x, e1 = c.y, e2 = c.z, e3 = c.w;
        unsigned long long w10 = 0, w11 = 0, w12 = 0, w13 = 0;
        unsigned long long w20 = 0, w21 = 0, w22 = 0, w23 = 0;
        if (a1) {
            w10 = __ldg(pA + ((e0 & 1023u) << 9));
            w11 = __ldg(pA + ((e1 & 1023u) << 9));
            w12 = __ldg(pA + ((e2 & 1023u) << 9));
            w13 = __ldg(pA + ((e3 & 1023u) << 9));
        }
        if (a2) {
            w20 = __ldg(pB + ((e0 & 1023u) << 9));
            w21 = __ldg(pB + ((e1 & 1023u) << 9));
            w22 = __ldg(pB + ((e2 & 1023u) << 9));
            w23 = __ldg(pB + ((e3 & 1023u) << 9));
        }
        const ulonglong2* tp = tbl + (e0 >> 10) * 4;
        ulonglong2 tA = tp[0], tB = tp[1], tC = tp[2], tD = tp[3];
        for (int b = 0; b < nb; b++) {
            unsigned f1 = e1, f2 = e2, f3 = e3;
            unsigned long long v10 = w10, v11 = w11, v12 = w12, v13 = w13;
            unsigned long long v20 = w20, v21 = w21, v22 = w22, v23 = w23;
            bool more = (b + 1 < nb);
            if (more) {
                uint4 n = *reinterpret_cast<const uint4*>(list + 4 * (b + 1));
                e0 = n.x; e1 = n.y; e2 = n.z; e3 = n.w;
                if (a1) {
                    w10 = __ldg(pA + ((e0 & 1023u) << 9));
                    w11 = __ldg(pA + ((e1 & 1023u) << 9));
                    w12 = __ldg(pA + ((e2 & 1023u) << 9));
                    w13 = __ldg(pA + ((e3 & 1023u) << 9));
                }
                if (a2) {
                    w20 = __ldg(pB + ((e0 & 1023u) << 9));
                    w21 = __ldg(pB + ((e1 & 1023u) << 9));
                    w22 = __ldg(pB + ((e2 & 1023u) << 9));
                    w23 = __ldg(pB + ((e3 & 1023u) << 9));
                }
            }
            ulonglong2 uA, uB, uC, uD;
            tp = tbl + (f1 >> 10) * 4;
            uA = tp[0]; uB = tp[1]; uC = tp[2]; uD = tp[3];
            ROW_FF(tA, tB, tC, tD, v10, v20);
            tp = tbl + (f2 >> 10) * 4;
            tA = tp[0]; tB = tp[1]; tC = tp[2]; tD = tp[3];
            ROW_FF(uA, uB, uC, uD, v11, v21);
            tp = tbl + (f3 >> 10) * 4;
            uA = tp[0]; uB = tp[1]; uC = tp[2]; uD = tp[3];
            ROW_FF(tA, tB, tC, tD, v12, v22);
            if (more) {
                tp = tbl + (e0 >> 10) * 4;
                tA = tp[0]; tB = tp[1]; tC = tp[2]; tD = tp[3];
            }
            ROW_FF(uA, uB, uC, uD, v13, v23);
        }
    }
    for (int i = nb << 2; i < cnt; i++) {
        unsigned e = list[i];
        unsigned long long v1 = a1 ? __ldg(pA + ((e & 1023u) << 9)) : 0ull;
        unsigned long long v2 = a2 ? __ldg(pB + ((e & 1023u) << 9)) : 0ull;
        const ulonglong2* tp = tbl + (e >> 10) * 4;
        ulonglong2 tA = tp[0], tB = tp[1], tC = tp[2], tD = tp[3];
        ROW_FF(tA, tB, tC, tD, v1, v2);
    }
}

// ---------------------------------------------------------------------------
__global__ void __launch_bounds__(NTHR) snn_kernel(
    const float* __restrict__ input,
    const float* __restrict__ W1, const float* __restrict__ b1,
    const float* __restrict__ b2, const float* __restrict__ b3,
    const float* __restrict__ W4, const float* __restrict__ b4,
    float* __restrict__ out) {
    extern __shared__ unsigned char smemraw[];
    ulonglong2* tbl = reinterpret_cast<ulonglong2*>(smemraw + SM_TBL);
    ulonglong2* dcsh = reinterpret_cast<ulonglong2*>(smemraw + SM_DC);
    unsigned* listA = reinterpret_cast<unsigned*>(smemraw + SM_LISTA);
    unsigned* listB = reinterpret_cast<unsigned*>(smemraw + SM_LISTB);
    int* s_warp = reinterpret_cast<int*>(smemraw + SM_WARP);
    float* xsh = reinterpret_cast<float*>(smemraw + SM_XSH);
    float4* s_red4 = reinterpret_cast<float4*>(smemraw + SM_RED);

    const int tid = threadIdx.x;
    const int n0 = blockIdx.x * G;
    const int h0 = 4 * tid;  // layer-1 units

    // build mask->floatpair table (once): tbl[m][g] = (bit_g, bit_g)
    {
        int m = tid;
#pragma unroll
        for (int q = 0; q < 4; q++) {
            F2U lo, hi;
            float f0 = ((m >> (2 * q)) & 1) ? 1.0f : 0.0f;
            float f1 = ((m >> (2 * q + 1)) & 1) ? 1.0f : 0.0f;
            lo.f = make_float2(f0, f0);
            hi.f = make_float2(f1, f1);
            tbl[m * 4 + q] = make_ulonglong2(lo.u, hi.u);
        }
    }

    // col maps: slot k -> col c = 512*(k>>1) + 2*tid + (k&1)
    int h2s[4], h3s[4];
    float b2v[4], b3v[4];
#pragma unroll
    for (int k = 0; k < 4; k++) {
        int c = 512 * (k >> 1) + 2 * tid + (k & 1);
        h2s[k] = __ldg(&g_u2[c]);
        h3s[k] = __ldg(&g_u3[c]);
        b2v[k] = __ldg(b2 + h2s[k]);
        b3v[k] = __ldg(b3 + h3s[k]);
    }
    unsigned long long bp2L, bp2H, bp3L, bp3H;
    {
        F2U a, b, c, d;
        a.f = make_float2(b2v[0], b2v[1]); bp2L = a.u;
        b.f = make_float2(b2v[2], b2v[3]); bp2H = b.u;
        c.f = make_float2(b3v[0], b3v[1]); bp3L = c.u;
        d.f = make_float2(b3v[2], b3v[3]); bp3H = d.u;
    }

    float m1[4][G], m2[4][G], m3[4][G];
#pragma unroll
    for (int k = 0; k < 4; k++)
#pragma unroll
        for (int g = 0; g < G; g++) {
            m1[k][g] = 0.f; m2[k][g] = 0.f; m3[k][g] = 0.f;
        }
    unsigned ss1l[4] = {0,0,0,0}, ss1h[4] = {0,0,0,0};
    unsigned ss2l[4] = {0,0,0,0}, ss2h[4] = {0,0,0,0};
    unsigned ss3l[4] = {0,0,0,0}, ss3h[4] = {0,0,0,0};

    const float4* W14 = reinterpret_cast<const float4*>(W1);
    const unsigned long long* pA2 =
        reinterpret_cast<const unsigned long long*>(g_W2J) + tid;
    const unsigned long long* pB2 = pA2 + 256;
    const unsigned long long* pA3 =
        reinterpret_cast<const unsigned long long*>(g_W3J) + tid;
    const unsigned long long* pB3 = pA3 + 256;
    const int ra = 64 * (tid >> 5);  // warp region start (pair1)

    // constant layer-1 drive (t >= 12 uses input slice at 776)
    if (tid < G * 8)
        xsh[tid] = __ldg(input + (n0 + (tid >> 3)) * 784 + 776 + (tid & 7));
    __syncthreads();
    {
        float4 bq1 = __ldg(reinterpret_cast<const float4*>(b1) + tid);
        float w1r[4][8];
#pragma unroll
        for (int k = 0; k < 4; k++) {
            float4 a = __ldg(W14 + (h0 + k) * 2);
            float4 c = __ldg(W14 + (h0 + k) * 2 + 1);
            w1r[k][0] = a.x; w1r[k][1] = a.y; w1r[k][2] = a.z; w1r[k][3] = a.w;
            w1r[k][4] = c.x; w1r[k][5] = c.y; w1r[k][6] = c.z; w1r[k][7] = c.w;
        }
        float bb[4] = {bq1.x, bq1.y, bq1.z, bq1.w};
#pragma unroll
        for (int g = 0; g < G; g++) {
            const float* x = &xsh[g * 8];
            float s[4];
#pragma unroll
            for (int k = 0; k < 4; k++) {
                float acc = bb[k];
#pragma unroll
                for (int i = 0; i < 8; i++) acc += x[i] * w1r[k][i];
                s[k] = acc;
            }
            F2U lo, hi;
            lo.f = make_float2(s[0], s[1]);
            hi.f = make_float2(s[2], s[3]);
            dcsh[g * NTHR + tid] = make_ulonglong2(lo.u, hi.u);
        }
    }
    __syncthreads();

    int w0 = 66;    // (33*t + 66) % 98 at t=0
    int g3lo = 25;  // (25*tau + 25) % 49 at tau=0

    for (int t = 0; t < TSTEPS; t++) {
        const int par = t & 1;

        // ---------- layer 1 drive ----------
        unsigned long long d1L[G], d1H[G];
        if (t < 12) {
            if (tid < G * 8)
                xsh[tid] =
                    __ldg(input + (n0 + (tid >> 3)) * 784 + t * 8 + (tid & 7));
            __syncthreads();
            float4 bq1 = __ldg(reinterpret_cast<const float4*>(b1) + tid);
            float w1r[4][8];
#pragma unroll
            for (int k = 0; k < 4; k++) {
                float4 a = __ldg(W14 + (h0 + k) * 2);
                float4 c = __ldg(W14 + (h0 + k) * 2 + 1);
                w1r[k][0] = a.x; w1r[k][1] = a.y; w1r[k][2] = a.z; w1r[k][3] = a.w;
                w1r[k][4] = c.x; w1r[k][5] = c.y; w1r[k][6] = c.z; w1r[k][7] = c.w;
            }
            float bb[4] = {bq1.x, bq1.y, bq1.z, bq1.w};
#pragma unroll
            for (int g = 0; g < G; g++) {
                const float* x = &xsh[g * 8];
                float s[4];
#pragma unroll
                for (int k = 0; k < 4; k++) {
                    float acc = bb[k];
#pragma unroll
                    for (int i = 0; i < 8; i++) acc += x[i] * w1r[k][i];
                    s[k] = acc;
                }
                F2U lo, hi;
                lo.f = make_float2(s[0], s[1]);
                hi.f = make_float2(s[2], s[3]);
                d1L[g] = lo.u;
                d1H[g] = hi.u;
            }
            __syncthreads();
        } else {
#pragma unroll
            for (int g = 0; g < G; g++) {
                ulonglong2 v = dcsh[g * NTHR + tid];
                d1L[g] = v.x;
                d1H[g] = v.y;
            }
        }

        // ---------- layer 1 update (eligible k = par, par+2) ----------
        unsigned mk0 = 0, mk2 = 0;
        if (par == 0) {
#pragma unroll
            for (int g = 0; g < G; g++) {
                F2U uL, uH; uL.u = d1L[g]; uH.u = d1H[g];
                float na = m1[0][g] * 0.5f + uL.f.x;
                float nc = m1[2][g] * 0.5f + uH.f.x;
                m1[0][g] = na; m1[2][g] = nc;
                if (na > 0.5f) mk0 |= 1u << g;
                if (nc > 0.5f) mk2 |= 1u << g;
            }
            ss1l[0] += spread4(mk0); ss1h[0] += spread4(mk0 >> 4);
            ss1l[2] += spread4(mk2); ss1h[2] += spread4(mk2 >> 4);
        } else {
#pragma unroll
            for (int g = 0; g < G; g++) {
                F2U uL, uH; uL.u = d1L[g]; uH.u = d1H[g];
                float na = m1[1][g] * 0.5f + uL.f.y;
                float nc = m1[3][g] * 0.5f + uH.f.y;
                m1[1][g] = na; m1[3][g] = nc;
                if (na > 0.5f) mk0 |= 1u << g;
                if (nc > 0.5f) mk2 |= 1u << g;
            }
            ss1l[1] += spread4(mk0); ss1h[1] += spread4(mk0 >> 4);
            ss1l[3] += spread4(mk2); ss1h[3] += spread4(mk2 >> 4);
        }

        int excl, cnt;
        block_scan((mk0 ? 1 : 0) + (mk2 ? 1 : 0), tid, s_warp, excl, cnt);
        {
            int p = excl;
            if (mk0) listA[p++] = (mk0 << 10) | (unsigned)(h0 + par);
            if (mk2) listA[p] = (mk2 << 10) | (unsigned)(h0 + par + 2);
        }
        __syncthreads();

        // ---------- layer 2: region gather + update ----------
        {
            int lo = __ldg(&g_S2[w0]);
            int hiI = w0 + 33;
            bool wrap = hiI > 98;
            int hi = wrap ? __ldg(&g_S2[hiI - 98]) : __ldg(&g_S2[hiI]);
            bool a1 = wrap ? (ra < hi || ra + 64 > lo)
                           : (ra + 64 > lo && ra < hi);
            int rb = 512 + ra;
            bool a2 = wrap ? (rb < hi || rb + 64 > lo)
                           : (rb + 64 > lo && rb < hi);
            unsigned long long acc1[8], acc2[8];
#pragma unroll
            for (int g = 0; g < G; g++) { acc1[g] = bp2L; acc2[g] = bp2H; }
            gatherP(listA, cnt, pA2, pB2, tbl, a1, a2, acc1, acc2);

            unsigned msk[4];
            int cl = 0;
#pragma unroll
            for (int k = 0; k < 4; k++) {
                int c = 512 * (k >> 1) + 2 * tid + (k & 1);
                bool el = wrap ? (c >= lo || c < hi) : (c >= lo && c < hi);
                msk[k] = 0;
                if (el) {
                    unsigned mm = 0;
#pragma unroll
                    for (int g = 0; g < G; g++) {
                        F2U u;
                        u.u = (k >> 1) ? acc2[g] : acc1[g];
                        float d = (k & 1) ? u.f.y : u.f.x;
                        float nm = m2[k][g] * 0.5f + d;
                        m2[k][g] = nm;
                        if (nm > 0.5f) mm |= 1u << g;
                    }
                    msk[k] = mm;
                    ss2l[k] += spread4(mm);
                    ss2h[k] += spread4(mm >> 4);
                    cl += (mm ? 1 : 0);
                }
            }
            block_scan(cl, tid, s_warp, excl, cnt);
            {
                int p = excl;
#pragma unroll
                for (int k = 0; k < 4; k++)
                    if (msk[k]) listB[p++] = (msk[k] << 10) | (unsigned)h2s[k];
            }
            __syncthreads();
        }

        // ---------- layer 3: region gather + update ----------
        {
            int lo = __ldg(&g_S3[par][g3lo]);
            int hiI = g3lo + 25;
            bool wrap = hiI > 49;
            int hi = wrap ? __ldg(&g_S3[par][hiI - 49]) : __ldg(&g_S3[par][hiI]);
            int r1 = ra, r2 = 512 + ra;
            bool a1 = (par == 0) && (wrap ? (r1 < hi || r1 + 64 > lo)
                                          : (r1 + 64 > lo && r1 < hi));
            bool a2 = (par == 1) && (wrap ? (r2 < hi || r2 + 64 > lo)
                                          : (r2 + 64 > lo && r2 < hi));
            unsigned long long acc1[8], acc2[8];
#pragma unroll
            for (int g = 0; g < G; g++) { acc1[g] = bp3L; acc2[g] = bp3H; }
            gatherP(listB, cnt, pA3, pB3, tbl, a1, a2, acc1, acc2);

#pragma unroll
            for (int k = 0; k < 4; k++) {
                int p = k >> 1;
                int c = 512 * p + 2 * tid + (k & 1);
                bool el = (p == par) &&
                          (wrap ? (c >= lo || c < hi) : (c >= lo && c < hi));
                if (el) {
                    unsigned mm = 0;
#pragma unroll
                    for (int g = 0; g < G; g++) {
                        F2U u;
                        u.u = p ? acc2[g] : acc1[g];
                        float d = (k & 1) ? u.f.y : u.f.x;
                        float nm = m3[k][g] * 0.5f + d;
                        m3[k][g] = nm;
                        if (nm > 0.5f) mm |= 1u << g;
                    }
                    ss3l[k] += spread4(mm);
                    ss3h[k] += spread4(mm >> 4);
                }
            }
        }

        // advance windows
        w0 += 33; if (w0 >= 98) w0 -= 98;
        if (par == 1) { g3lo += 25; if (g3lo >= 49) g3lo -= 49; }
    }

    // ------------------------- epilogue -------------------------
    const float inv = 1.0f / 98.0f;

#pragma unroll
    for (int g = 0; g < G; g++) {
        int sh = 8 * (g & 3);
        const unsigned* l1 = (g < 4) ? ss1l : ss1h;
        float4 v1 = make_float4((float)((l1[0] >> sh) & 255u) * inv,
                                (float)((l1[1] >> sh) & 255u) * inv,
                                (float)((l1[2] >> sh) & 255u) * inv,
                                (float)((l1[3] >> sh) & 255u) * inv);
        *reinterpret_cast<float4*>(out + 10240 + (n0 + g) * HID + h0) = v1;
    }
#pragma unroll
    for (int k = 0; k < 4; k++) {
#pragma unroll
        for (int g = 0; g < G; g++) {
            int sh = 8 * (g & 3);
            float a2 = (float)(((g < 4 ? ss2l[k] : ss2h[k]) >> sh) & 255u);
            float a3 = (float)(((g < 4 ? ss3l[k] : ss3h[k]) >> sh) & 255u);
            out[10240 + 1048576 + (n0 + g) * HID + h2s[k]] = a2 * inv;
            out[10240 + 2097152 + (n0 + g) * HID + h3s[k]] = a3 * inv;
        }
    }

    float s3f[4][G];
#pragma unroll
    for (int k = 0; k < 4; k++)
#pragma unroll
        for (int g = 0; g < G; g++)
            s3f[k][g] =
                (float)(((g < 4 ? ss3l[k] : ss3h[k]) >> (8 * (g & 3))) & 255u);

    const int lane = tid & 31, wid = tid >> 5;

    for (int o = 0; o < 10; o++) {
        float w4s[4];
#pragma unroll
        for (int k = 0; k < 4; k++) w4s[k] = __ldg(W4 + o * HID + h3s[k]);
#pragma unroll
        for (int half = 0; half < 2; half++) {
            float4 v;
            v.x = s3f[0][half * 4 + 0] * w4s[0] + s3f[1][half * 4 + 0] * w4s[1] +
                  s3f[2][half * 4 + 0] * w4s[2] + s3f[3][half * 4 + 0] * w4s[3];
            v.y = s3f[0][half * 4 + 1] * w4s[0] + s3f[1][half * 4 + 1] * w4s[1] +
                  s3f[2][half * 4 + 1] * w4s[2] + s3f[3][half * 4 + 1] * w4s[3];
            v.z = s3f[0][half * 4 + 2] * w4s[0] + s3f[1][half * 4 + 2] * w4s[1] +
                  s3f[2][half * 4 + 2] * w4s[2] + s3f[3][half * 4 + 2] * w4s[3];
            v.w = s3f[0][half * 4 + 3] * w4s[0] + s3f[1][half * 4 + 3] * w4s[1] +
                  s3f[2][half * 4 + 3] * w4s[2] + s3f[3][half * 4 + 3] * w4s[3];
#pragma unroll
            for (int off = 16; off > 0; off >>= 1) {
                v.x += __shfl_down_sync(0xffffffffu, v.x, off);
                v.y += __shfl_down_sync(0xffffffffu, v.y, off);
                v.z += __shfl_down_sync(0xffffffffu, v.z, off);
                v.w += __shfl_down_sync(0xffffffffu, v.w, off);
            }
            if (lane == 0) s_red4[wid] = v;
            __syncthreads();
            if (tid == 0) {
                float4 s = make_float4(0, 0, 0, 0);
#pragma unroll
                for (int w = 0; w < 8; w++) {
                    s.x += s_red4[w].x; s.y += s_red4[w].y;
                    s.z += s_red4[w].z; s.w += s_red4[w].w;
                }
                float bo = __ldg(b4 + o);
                out[(n0 + half * 4 + 0) * 10 + o] = s.x / 98.0f + bo;
                out[(n0 + half * 4 + 1) * 10 + o] = s.y / 98.0f + bo;
                out[(n0 + half * 4 + 2) * 10 + o] = s.z / 98.0f + bo;
                out[(n0 + half * 4 + 3) * 10 + o] = s.w / 98.0f + bo;
            }
            __syncthreads();
        }
    }

    unsigned c1 = 0, c2 = 0, c3 = 0;
#pragma unroll
    for (int k = 0; k < 4; k++) {
        c1 = bytesum(ss1l[k], c1); c1 = bytesum(ss1h[k], c1);
        c2 = bytesum(ss2l[k], c2); c2 = bytesum(ss2h[k], c2);
        c3 = bytesum(ss3l[k], c3); c3 = bytesum(ss3h[k], c3);
    }
    {
        float4 v = make_float4((float)c1, (float)c2, (float)c3, 0.0f);
#pragma unroll
        for (int off = 16; off > 0; off >>= 1) {
            v.x += __shfl_down_sync(0xffffffffu, v.x, off);
            v.y += __shfl_down_sync(0xffffffffu, v.y, off);
            v.z += __shfl_down_sync(0xffffffffu, v.z, off);
        }
        if (lane == 0) s_red4[wid] = v;
        __syncthreads();
        if (tid == 0) {
            float s0 = 0, s1 = 0, s2 = 0;
#pragma unroll
            for (int w = 0; w < 8; w++) {
                s0 += s_red4[w].x; s1 += s_red4[w].y; s2 += s_red4[w].z;
            }
            atomicAdd(&g_fr[0], s0);
            atomicAdd(&g_fr[1], s1);
            atomicAdd(&g_fr[2], s2);
        }
    }
}

__global__ void finalize_kernel(float* __restrict__ out) {
    if (threadIdx.x < 3)
        out[3155968 + threadIdx.x] = g_fr[threadIdx.x] / 102760448.0f;
}

extern "C" void kernel_launch(void* const* d_in, const int* in_sizes, int n_in,
                              void* d_out, int out_size) {
    const float* input = (const float*)d_in[0];
    const float* W1 = (const float*)d_in[1];
    const float* b1 = (const float*)d_in[2];
    const float* W2 = (const float*)d_in[3];
    const float* b2 = (const float*)d_in[4];
    const float* W3 = (const float*)d_in[5];
    const float* b3 = (const float*)d_in[6];
    const float* W4 = (const float*)d_in[7];
    const float* b4 = (const float*)d_in[8];
    (void)in_sizes; (void)n_in; (void)out_size;

    cudaFuncSetAttribute(snn_kernel,
                         cudaFuncAttributeMaxDynamicSharedMemorySize, SM_TOTAL);
    init_tables<<<1, 1>>>();
    dim3 pgrid(HID / 32, HID / 32, 2);
    prep_kernel<<<pgrid, dim3(32, 32)>>>(W2, W3);
    snn_kernel<<<NCTA, NTHR, SM_TOTAL>>>(input, W1, b1, b2, b3, W4, b4,
                                         (float*)d_out);
    finalize_kernel<<<1, 32>>>((float*)d_out);
}

// round 11
// speedup vs baseline: 1.2689x; 1.2689x over previous
#include <cuda_runtime.h>

#define HID 1024
#define NSAMP 1024
#define TSTEPS 98
#define G 8            // samples per CTA
#define NTHR 256       // threads per CTA
#define NCTA (NSAMP / G)

__device__ float g_W2J[HID * HID];  // [src h][reordered dest col]
__device__ float g_W3J[HID * HID];
__device__ int g_u2[HID];           // col -> dest unit (layer 2 ordering)
__device__ int g_u3[HID];           // col -> dest unit (layer 3 ordering)
__device__ int g_S2[99];            // group prefix sums (98 groups)
__device__ int g_S3[2][50];         // per-parity group prefix sums
__device__ float g_fr[3];

// ---------------------------------------------------------------------------
__global__ void init_tables() {
    if (threadIdx.x != 0 || blockIdx.x != 0) return;
    int s = 0;
    for (int g = 0; g < 98; g++) {
        g_S2[g] = s;
        int rho = (3 * g) % 98;
        int cnt = (rho < 44) ? 11 : 10;
        for (int i = 0; i < cnt; i++) g_u2[s + i] = rho + 98 * i;
        s += cnt;
    }
    g_S2[98] = s;
    for (int p = 0; p < 2; p++) {
        int sp = 512 * p;
        for (int g3 = 0; g3 < 49; g3++) {
            g_S3[p][g3] = sp;
            int q = (2 * g3) % 49;
            int rho = 2 * q + p;
            int cnt = (rho < 44) ? 11 : 10;
            for (int i = 0; i < cnt; i++) g_u3[sp + i] = rho + 98 * i;
            sp += cnt;
        }
        g_S3[p][49] = sp;
    }
    g_fr[0] = 0.0f; g_fr[1] = 0.0f; g_fr[2] = 0.0f;
}

// ---------------------------------------------------------------------------
__global__ void prep_kernel(const float* __restrict__ W2,
                            const float* __restrict__ W3) {
    __shared__ float tile[32][33];
    __shared__ int uu[32];
    const float* src = (blockIdx.z == 0) ? W2 : W3;
    float* dst = (blockIdx.z == 0) ? g_W2J : g_W3J;
    const int* umap = (blockIdx.z == 0) ? g_u2 : g_u3;
    int c0 = blockIdx.x * 32, h0 = blockIdx.y * 32;
    int tx = threadIdx.x, ty = threadIdx.y;
    if (ty == 0) uu[tx] = umap[c0 + tx];
    __syncthreads();
    tile[ty][tx] = src[uu[ty] * HID + h0 + tx];
    __syncthreads();
    dst[(h0 + ty) * HID + c0 + tx] = tile[tx][ty];
}

// ---------------------------------------------------------------------------
static __device__ __forceinline__ unsigned long long addf32x2(
    unsigned long long a, unsigned long long b) {
    unsigned long long o;
    asm("add.rn.f32x2 %0, %1, %2;" : "=l"(o) : "l"(a), "l"(b));
    return o;
}

static __device__ __forceinline__ unsigned spread4(unsigned m) {
    return ((m & 0xFu) * 0x00204081u) & 0x01010101u;
}

static __device__ __forceinline__ unsigned bytesum(unsigned v, unsigned c) {
    unsigned ones = 0x01010101u;
    unsigned r;
    asm("dp4a.u32.u32 %0, %1, %2, %3;" : "=r"(r) : "r"(v), "r"(ones), "r"(c));
    return r;
}

// exclusive scan over 256 threads (8 warps)
static __device__ __forceinline__ void block_scan(int v, int tid, int* s_warp,
                                                  int& excl, int& total) {
    int lane = tid & 31, wid = tid >> 5;
    int x = v;
#pragma unroll
    for (int o = 1; o < 32; o <<= 1) {
        int y = __shfl_up_sync(0xffffffffu, x, o);
        if (lane >= o) x += y;
    }
    __syncthreads();
    if (lane == 31) s_warp[wid] = x;
    __syncthreads();
    int pre = 0, tot = 0;
#pragma unroll
    for (int w = 0; w < 8; w++) {
        int sw = s_warp[w];
        pre += (w < wid) ? sw : 0;
        tot += sw;
    }
    excl = pre + x - v;
    total = tot;
}

union F2U { unsigned long long u; float2 f; };

// one row: 8 mask tests, predicated packed adds into the active pair accs
#define ACCR(e, v1, v2)                                                     \
    do {                                                                    \
        unsigned _m = (e) >> 10;                                            \
        if (_m & 1u)   { if (A1) acc1[0] = addf32x2(acc1[0], (v1));         \
                         if (A2) acc2[0] = addf32x2(acc2[0], (v2)); }       \
        if (_m & 2u)   { if (A1) acc1[1] = addf32x2(acc1[1], (v1));         \
                         if (A2) acc2[1] = addf32x2(acc2[1], (v2)); }       \
        if (_m & 4u)   { if (A1) acc1[2] = addf32x2(acc1[2], (v1));         \
                         if (A2) acc2[2] = addf32x2(acc2[2], (v2)); }       \
        if (_m & 8u)   { if (A1) acc1[3] = addf32x2(acc1[3], (v1));         \
                         if (A2) acc2[3] = addf32x2(acc2[3], (v2)); }       \
        if (_m & 16u)  { if (A1) acc1[4] = addf32x2(acc1[4], (v1));         \
                         if (A2) acc2[4] = addf32x2(acc2[4], (v2)); }       \
        if (_m & 32u)  { if (A1) acc1[5] = addf32x2(acc1[5], (v1));         \
                         if (A2) acc2[5] = addf32x2(acc2[5], (v2)); }       \
        if (_m & 64u)  { if (A1) acc1[6] = addf32x2(acc1[6], (v1));         \
                         if (A2) acc2[6] = addf32x2(acc2[6], (v2)); }       \
        if (_m & 128u) { if (A1) acc1[7] = addf32x2(acc1[7], (v1));         \
                         if (A2) acc2[7] = addf32x2(acc2[7], (v2)); }       \
    } while (0)

// union-row gather, pair columns, depth-4 weight pipeline, compile-time pair
// activity (A1: cols 2tid..2tid+1 via pA; A2: +512 via pB)
template <bool A1, bool A2>
static __device__ __forceinline__ void gather_impl(
    const unsigned* __restrict__ list, int cnt,
    const unsigned long long* __restrict__ pA,
    const unsigned long long* __restrict__ pB,
    unsigned long long* acc1, unsigned long long* acc2) {
    const int nb = cnt >> 2;
    if (nb > 0) {
        uint4 c = *reinterpret_cast<const uint4*>(list);
        unsigned e0 = c.x, e1 = c.y, e2 = c.z, e3 = c.w;
        unsigned long long w10 = 0, w11 = 0, w12 = 0, w13 = 0;
        unsigned long long w20 = 0, w21 = 0, w22 = 0, w23 = 0;
        if (A1) {
            w10 = __ldg(pA + ((e0 & 1023u) << 9));
            w11 = __ldg(pA + ((e1 & 1023u) << 9));
            w12 = __ldg(pA + ((e2 & 1023u) << 9));
            w13 = __ldg(pA + ((e3 & 1023u) << 9));
        }
        if (A2) {
            w20 = __ldg(pB + ((e0 & 1023u) << 9));
            w21 = __ldg(pB + ((e1 & 1023u) << 9));
            w22 = __ldg(pB + ((e2 & 1023u) << 9));
            w23 = __ldg(pB + ((e3 & 1023u) << 9));
        }
        for (int b = 0; b < nb; b++) {
            unsigned f0 = e0, f1 = e1, f2 = e2, f3 = e3;
            unsigned long long v10 = w10, v11 = w11, v12 = w12, v13 = w13;
            unsigned long long v20 = w20, v21 = w21, v22 = w22, v23 = w23;
            if (b + 1 < nb) {
                uint4 n = *reinterpret_cast<const uint4*>(list + 4 * (b + 1));
                e0 = n.x; e1 = n.y; e2 = n.z; e3 = n.w;
                if (A1) {
                    w10 = __ldg(pA + ((e0 & 1023u) << 9));
                    w11 = __ldg(pA + ((e1 & 1023u) << 9));
                    w12 = __ldg(pA + ((e2 & 1023u) << 9));
                    w13 = __ldg(pA + ((e3 & 1023u) << 9));
                }
                if (A2) {
                    w20 = __ldg(pB + ((e0 & 1023u) << 9));
                    w21 = __ldg(pB + ((e1 & 1023u) << 9));
                    w22 = __ldg(pB + ((e2 & 1023u) << 9));
                    w23 = __ldg(pB + ((e3 & 1023u) << 9));
                }
            }
            ACCR(f0, v10, v20);
            ACCR(f1, v11, v21);
            ACCR(f2, v12, v22);
            ACCR(f3, v13, v23);
        }
    }
    for (int i = nb << 2; i < cnt; i++) {
        unsigned e = list[i];
        unsigned long long v1 = A1 ? __ldg(pA + ((e & 1023u) << 9)) : 0ull;
        unsigned long long v2 = A2 ? __ldg(pB + ((e & 1023u) << 9)) : 0ull;
        ACCR(e, v1, v2);
    }
}

static __device__ __forceinline__ void gatherP(
    const unsigned* __restrict__ list, int cnt,
    const unsigned long long* __restrict__ pA,
    const unsigned long long* __restrict__ pB, bool a1, bool a2,
    unsigned long long* acc1, unsigned long long* acc2) {
    if (cnt <= 0) return;
    if (a1) {
        if (a2) gather_impl<true, true>(list, cnt, pA, pB, acc1, acc2);
        else gather_impl<true, false>(list, cnt, pA, pB, acc1, acc2);
    } else if (a2) {
        gather_impl<false, true>(list, cnt, pA, pB, acc1, acc2);
    }
}

// ---------------------------------------------------------------------------
__global__ void __launch_bounds__(NTHR) snn_kernel(
    const float* __restrict__ input,
    const float* __restrict__ W1, const float* __restrict__ b1,
    const float* __restrict__ b2, const float* __restrict__ b3,
    const float* __restrict__ W4, const float* __restrict__ b4,
    float* __restrict__ out) {
    __shared__ __align__(16) unsigned listA[HID];
    __shared__ __align__(16) unsigned listB[HID];
    __shared__ int s_warp[8];
    __shared__ float xsh[G * 8];
    __shared__ float4 s_red4[8];
    __shared__ __align__(16) ulonglong2 dcsh[G * NTHR];  // const L1 drive

    const int tid = threadIdx.x;
    const int n0 = blockIdx.x * G;
    const int h0 = 4 * tid;  // layer-1 units

    // col maps: slot k -> col c = 512*(k>>1) + 2*tid + (k&1)
    int h2s[4], h3s[4];
    float b2v[4], b3v[4];
#pragma unroll
    for (int k = 0; k < 4; k++) {
        int c = 512 * (k >> 1) + 2 * tid + (k & 1);
        h2s[k] = __ldg(&g_u2[c]);
        h3s[k] = __ldg(&g_u3[c]);
        b2v[k] = __ldg(b2 + h2s[k]);
        b3v[k] = __ldg(b3 + h3s[k]);
    }
    unsigned long long bp2L, bp2H, bp3L, bp3H;
    {
        F2U a, b, c, d;
        a.f = make_float2(b2v[0], b2v[1]); bp2L = a.u;
        b.f = make_float2(b2v[2], b2v[3]); bp2H = b.u;
        c.f = make_float2(b3v[0], b3v[1]); bp3L = c.u;
        d.f = make_float2(b3v[2], b3v[3]); bp3H = d.u;
    }

    float m1[4][G], m2[4][G], m3[4][G];
#pragma unroll
    for (int k = 0; k < 4; k++)
#pragma unroll
        for (int g = 0; g < G; g++) {
            m1[k][g] = 0.f; m2[k][g] = 0.f; m3[k][g] = 0.f;
        }
    unsigned ss1l[4] = {0,0,0,0}, ss1h[4] = {0,0,0,0};
    unsigned ss2l[4] = {0,0,0,0}, ss2h[4] = {0,0,0,0};
    unsigned ss3l[4] = {0,0,0,0}, ss3h[4] = {0,0,0,0};

    const float4* W14 = reinterpret_cast<const float4*>(W1);
    const unsigned long long* pA2 =
        reinterpret_cast<const unsigned long long*>(g_W2J) + tid;
    const unsigned long long* pB2 = pA2 + 256;
    const unsigned long long* pA3 =
        reinterpret_cast<const unsigned long long*>(g_W3J) + tid;
    const unsigned long long* pB3 = pA3 + 256;
    const int ra = 64 * (tid >> 5);  // warp region start (pair1 cols)

    // constant layer-1 drive (t >= 12 uses input slice at 776)
    if (tid < G * 8)
        xsh[tid] = __ldg(input + (n0 + (tid >> 3)) * 784 + 776 + (tid & 7));
    __syncthreads();
    {
        float4 bq1 = __ldg(reinterpret_cast<const float4*>(b1) + tid);
        float w1r[4][8];
#pragma unroll
        for (int k = 0; k < 4; k++) {
            float4 a = __ldg(W14 + (h0 + k) * 2);
            float4 c = __ldg(W14 + (h0 + k) * 2 + 1);
            w1r[k][0] = a.x; w1r[k][1] = a.y; w1r[k][2] = a.z; w1r[k][3] = a.w;
            w1r[k][4] = c.x; w1r[k][5] = c.y; w1r[k][6] = c.z; w1r[k][7] = c.w;
        }
        float bb[4] = {bq1.x, bq1.y, bq1.z, bq1.w};
#pragma unroll
        for (int g = 0; g < G; g++) {
            const float* x = &xsh[g * 8];
            float s[4];
#pragma unroll
            for (int k = 0; k < 4; k++) {
                float acc = bb[k];
#pragma unroll
                for (int i = 0; i < 8; i++) acc += x[i] * w1r[k][i];
                s[k] = acc;
            }
            F2U lo, hi;
            lo.f = make_float2(s[0], s[1]);
            hi.f = make_float2(s[2], s[3]);
            dcsh[g * NTHR + tid] = make_ulonglong2(lo.u, hi.u);
        }
    }
    __syncthreads();

    int w0 = 66;    // (33*t + 66) % 98 at t=0
    int g3lo = 25;  // (25*tau + 25) % 49 at tau=0

    for (int t = 0; t < TSTEPS; t++) {
        const int par = t & 1;

        // ---------- layer 1 drive ----------
        unsigned long long d1L[G], d1H[G];
        if (t < 12) {
            if (tid < G * 8)
                xsh[tid] =
                    __ldg(input + (n0 + (tid >> 3)) * 784 + t * 8 + (tid & 7));
            __syncthreads();
            float4 bq1 = __ldg(reinterpret_cast<const float4*>(b1) + tid);
            float w1r[4][8];
#pragma unroll
            for (int k = 0; k < 4; k++) {
                float4 a = __ldg(W14 + (h0 + k) * 2);
                float4 c = __ldg(W14 + (h0 + k) * 2 + 1);
                w1r[k][0] = a.x; w1r[k][1] = a.y; w1r[k][2] = a.z; w1r[k][3] = a.w;
                w1r[k][4] = c.x; w1r[k][5] = c.y; w1r[k][6] = c.z; w1r[k][7] = c.w;
            }
            float bb[4] = {bq1.x, bq1.y, bq1.z, bq1.w};
#pragma unroll
            for (int g = 0; g < G; g++) {
                const float* x = &xsh[g * 8];
                float s[4];
#pragma unroll
                for (int k = 0; k < 4; k++) {
                    float acc = bb[k];
#pragma unroll
                    for (int i = 0; i < 8; i++) acc += x[i] * w1r[k][i];
                    s[k] = acc;
                }
                F2U lo, hi;
                lo.f = make_float2(s[0], s[1]);
                hi.f = make_float2(s[2], s[3]);
                d1L[g] = lo.u;
                d1H[g] = hi.u;
            }
            __syncthreads();
        } else {
#pragma unroll
            for (int g = 0; g < G; g++) {
                ulonglong2 v = dcsh[g * NTHR + tid];
                d1L[g] = v.x;
                d1H[g] = v.y;
            }
        }

        // ---------- layer 1 update (eligible k = par, par+2) ----------
        unsigned mk0 = 0, mk2 = 0;
        if (par == 0) {
#pragma unroll
            for (int g = 0; g < G; g++) {
                F2U uL, uH; uL.u = d1L[g]; uH.u = d1H[g];
                float na = m1[0][g] * 0.5f + uL.f.x;
                float nc = m1[2][g] * 0.5f + uH.f.x;
                m1[0][g] = na; m1[2][g] = nc;
                if (na > 0.5f) mk0 |= 1u << g;
                if (nc > 0.5f) mk2 |= 1u << g;
            }
            ss1l[0] += spread4(mk0); ss1h[0] += spread4(mk0 >> 4);
            ss1l[2] += spread4(mk2); ss1h[2] += spread4(mk2 >> 4);
        } else {
#pragma unroll
            for (int g = 0; g < G; g++) {
                F2U uL, uH; uL.u = d1L[g]; uH.u = d1H[g];
                float na = m1[1][g] * 0.5f + uL.f.y;
                float nc = m1[3][g] * 0.5f + uH.f.y;
                m1[1][g] = na; m1[3][g] = nc;
                if (na > 0.5f) mk0 |= 1u << g;
                if (nc > 0.5f) mk2 |= 1u << g;
            }
            ss1l[1] += spread4(mk0); ss1h[1] += spread4(mk0 >> 4);
            ss1l[3] += spread4(mk2); ss1h[3] += spread4(mk2 >> 4);
        }

        int excl, cnt;
        block_scan((mk0 ? 1 : 0) + (mk2 ? 1 : 0), tid, s_warp, excl, cnt);
        {
            int p = excl;
            if (mk0) listA[p++] = (mk0 << 10) | (unsigned)(h0 + par);
            if (mk2) listA[p] = (mk2 << 10) | (unsigned)(h0 + par + 2);
        }
        __syncthreads();

        // ---------- layer 2: region gather + update ----------
        {
            int lo = __ldg(&g_S2[w0]);
            int hiI = w0 + 33;
            bool wrap = hiI > 98;
            int hi = wrap ? __ldg(&g_S2[hiI - 98]) : __ldg(&g_S2[hiI]);
            bool a1 = wrap ? (ra < hi || ra + 64 > lo)
                           : (ra + 64 > lo && ra < hi);
            int rb = 512 + ra;
            bool a2 = wrap ? (rb < hi || rb + 64 > lo)
                           : (rb + 64 > lo && rb < hi);
            unsigned long long acc1[8], acc2[8];
#pragma unroll
            for (int g = 0; g < G; g++) { acc1[g] = bp2L; acc2[g] = bp2H; }
            gatherP(listA, cnt, pA2, pB2, a1, a2, acc1, acc2);

            unsigned msk[4];
            int cl = 0;
#pragma unroll
            for (int k = 0; k < 4; k++) {
                int c = 512 * (k >> 1) + 2 * tid + (k & 1);
                bool el = wrap ? (c >= lo || c < hi) : (c >= lo && c < hi);
                msk[k] = 0;
                if (el) {
                    unsigned mm = 0;
#pragma unroll
                    for (int g = 0; g < G; g++) {
                        F2U u;
                        u.u = (k >> 1) ? acc2[g] : acc1[g];
                        float d = (k & 1) ? u.f.y : u.f.x;
                        float nm = m2[k][g] * 0.5f + d;
                        m2[k][g] = nm;
                        if (nm > 0.5f) mm |= 1u << g;
                    }
                    msk[k] = mm;
                    ss2l[k] += spread4(mm);
                    ss2h[k] += spread4(mm >> 4);
                    cl += (mm ? 1 : 0);
                }
            }
            block_scan(cl, tid, s_warp, excl, cnt);
            {
                int p = excl;
#pragma unroll
                for (int k = 0; k < 4; k++)
                    if (msk[k]) listB[p++] = (msk[k] << 10) | (unsigned)h2s[k];
            }
            __syncthreads();
        }

        // ---------- layer 3: region gather + update ----------
        {
            int lo = __ldg(&g_S3[par][g3lo]);
            int hiI = g3lo + 25;
            bool wrap = hiI > 49;
            int hi = wrap ? __ldg(&g_S3[par][hiI - 49]) : __ldg(&g_S3[par][hiI]);
            int r1 = ra, r2 = 512 + ra;
            bool a1 = (par == 0) && (wrap ? (r1 < hi || r1 + 64 > lo)
                                          : (r1 + 64 > lo && r1 < hi));
            bool a2 = (par == 1) && (wrap ? (r2 < hi || r2 + 64 > lo)
                                          : (r2 + 64 > lo && r2 < hi));
            unsigned long long acc1[8], acc2[8];
#pragma unroll
            for (int g = 0; g < G; g++) { acc1[g] = bp3L; acc2[g] = bp3H; }
            gatherP(listB, cnt, pA3, pB3, a1, a2, acc1, acc2);

#pragma unroll
            for (int k = 0; k < 4; k++) {
                int p = k >> 1;
                int c = 512 * p + 2 * tid + (k & 1);
                bool el = (p == par) &&
                          (wrap ? (c >= lo || c < hi) : (c >= lo && c < hi));
                if (el) {
                    unsigned mm = 0;
#pragma unroll
                    for (int g = 0; g < G; g++) {
                        F2U u;
                        u.u = p ? acc2[g] : acc1[g];
                        float d = (k & 1) ? u.f.y : u.f.x;
                        float nm = m3[k][g] * 0.5f + d;
                        m3[k][g] = nm;
                        if (nm > 0.5f) mm |= 1u << g;
                    }
                    ss3l[k] += spread4(mm);
                    ss3h[k] += spread4(mm >> 4);
                }
            }
        }

        // advance windows
        w0 += 33; if (w0 >= 98) w0 -= 98;
        if (par == 1) { g3lo += 25; if (g3lo >= 49) g3lo -= 49; }
    }

    // ------------------------- epilogue -------------------------
    const float inv = 1.0f / 98.0f;

#pragma unroll
    for (int g = 0; g < G; g++) {
        int sh = 8 * (g & 3);
        const unsigned* l1 = (g < 4) ? ss1l : ss1h;
        float4 v1 = make_float4((float)((l1[0] >> sh) & 255u) * inv,
                                (float)((l1[1] >> sh) & 255u) * inv,
                                (float)((l1[2] >> sh) & 255u) * inv,
                                (float)((l1[3] >> sh) & 255u) * inv);
        *reinterpret_cast<float4*>(out + 10240 + (n0 + g) * HID + h0) = v1;
    }
#pragma unroll
    for (int k = 0; k < 4; k++) {
#pragma unroll
        for (int g = 0; g < G; g++) {
            int sh = 8 * (g & 3);
            float a2 = (float)(((g < 4 ? ss2l[k] : ss2h[k]) >> sh) & 255u);
            float a3 = (float)(((g < 4 ? ss3l[k] : ss3h[k]) >> sh) & 255u);
            out[10240 + 1048576 + (n0 + g) * HID + h2s[k]] = a2 * inv;
            out[10240 + 2097152 + (n0 + g) * HID + h3s[k]] = a3 * inv;
        }
    }

    float s3f[4][G];
#pragma unroll
    for (int k = 0; k < 4; k++)
#pragma unroll
        for (int g = 0; g < G; g++)
            s3f[k][g] =
                (float)(((g < 4 ? ss3l[k] : ss3h[k]) >> (8 * (g & 3))) & 255u);

    const int lane = tid & 31, wid = tid >> 5;

    for (int o = 0; o < 10; o++) {
        float w4s[4];
#pragma unroll
        for (int k = 0; k < 4; k++) w4s[k] = __ldg(W4 + o * HID + h3s[k]);
#pragma unroll
        for (int half = 0; half < 2; half++) {
            float4 v;
            v.x = s3f[0][half * 4 + 0] * w4s[0] + s3f[1][half * 4 + 0] * w4s[1] +
                  s3f[2][half * 4 + 0] * w4s[2] + s3f[3][half * 4 + 0] * w4s[3];
            v.y = s3f[0][half * 4 + 1] * w4s[0] + s3f[1][half * 4 + 1] * w4s[1] +
                  s3f[2][half * 4 + 1] * w4s[2] + s3f[3][half * 4 + 1] * w4s[3];
            v.z = s3f[0][half * 4 + 2] * w4s[0] + s3f[1][half * 4 + 2] * w4s[1] +
                  s3f[2][half * 4 + 2] * w4s[2] + s3f[3][half * 4 + 2] * w4s[3];
            v.w = s3f[0][half * 4 + 3] * w4s[0] + s3f[1][half * 4 + 3] * w4s[1] +
                  s3f[2][half * 4 + 3] * w4s[2] + s3f[3][half * 4 + 3] * w4s[3];
#pragma unroll
            for (int off = 16; off > 0; off >>= 1) {
                v.x += __shfl_down_sync(0xffffffffu, v.x, off);
                v.y += __shfl_down_sync(0xffffffffu, v.y, off);
                v.z += __shfl_down_sync(0xffffffffu, v.z, off);
                v.w += __shfl_down_sync(0xffffffffu, v.w, off);
            }
            if (lane == 0) s_red4[wid] = v;
            __syncthreads();
            if (tid == 0) {
                float4 s = make_float4(0, 0, 0, 0);
#pragma unroll
                for (int w = 0; w < 8; w++) {
                    s.x += s_red4[w].x; s.y += s_red4[w].y;
                    s.z += s_red4[w].z; s.w += s_red4[w].w;
                }
                float bo = __ldg(b4 + o);
                out[(n0 + half * 4 + 0) * 10 + o] = s.x / 98.0f + bo;
                out[(n0 + half * 4 + 1) * 10 + o] = s.y / 98.0f + bo;
                out[(n0 + half * 4 + 2) * 10 + o] = s.z / 98.0f + bo;
                out[(n0 + half * 4 + 3) * 10 + o] = s.w / 98.0f + bo;
            }
            __syncthreads();
        }
    }

    unsigned c1 = 0, c2 = 0, c3 = 0;
#pragma unroll
    for (int k = 0; k < 4; k++) {
        c1 = bytesum(ss1l[k], c1); c1 = bytesum(ss1h[k], c1);
        c2 = bytesum(ss2l[k], c2); c2 = bytesum(ss2h[k], c2);
        c3 = bytesum(ss3l[k], c3); c3 = bytesum(ss3h[k], c3);
    }
    {
        float4 v = make_float4((float)c1, (float)c2, (float)c3, 0.0f);
#pragma unroll
        for (int off = 16; off > 0; off >>= 1) {
            v.x += __shfl_down_sync(0xffffffffu, v.x, off);
            v.y += __shfl_down_sync(0xffffffffu, v.y, off);
            v.z += __shfl_down_sync(0xffffffffu, v.z, off);
        }
        if (lane == 0) s_red4[wid] = v;
        __syncthreads();
        if (tid == 0) {
            float s0 = 0, s1 = 0, s2 = 0;
#pragma unroll
            for (int w = 0; w < 8; w++) {
                s0 += s_red4[w].x; s1 += s_red4[w].y; s2 += s_red4[w].z;
            }
            atomicAdd(&g_fr[0], s0);
            atomicAdd(&g_fr[1], s1);
            atomicAdd(&g_fr[2], s2);
        }
    }
}

__global__ void finalize_kernel(float* __restrict__ out) {
    if (threadIdx.x < 3)
        out[3155968 + threadIdx.x] = g_fr[threadIdx.x] / 102760448.0f;
}

extern "C" void kernel_launch(void* const* d_in, const int* in_sizes, int n_in,
                              void* d_out, int out_size) {
    const float* input = (const float*)d_in[0];
    const float* W1 = (const float*)d_in[1];
    const float* b1 = (const float*)d_in[2];
    const float* W2 = (const float*)d_in[3];
    const float* b2 = (const float*)d_in[4];
    const float* W3 = (const float*)d_in[5];
    const float* b3 = (const float*)d_in[6];
    const float* W4 = (const float*)d_in[7];
    const float* b4 = (const float*)d_in[8];
    (void)in_sizes; (void)n_in; (void)out_size;

    init_tables<<<1, 1>>>();
    dim3 pgrid(HID / 32, HID / 32, 2);
    prep_kernel<<<pgrid, dim3(32, 32)>>>(W2, W3);
    snn_kernel<<<NCTA, NTHR>>>(input, W1, b1, b2, b3, W4, b4, (float*)d_out);
    finalize_kernel<<<1, 32>>>((float*)d_out);
}

// round 12
// speedup vs baseline: 1.7679x; 1.3933x over previous
#include <cuda_runtime.h>

#define HID 1024
#define NSAMP 1024
#define TSTEPS 98
#define G 4            // samples per CTA
#define NTHR 256       // threads per CTA
#define NCTA (NSAMP / G)

__device__ float g_W2J[HID * HID];  // [src h][reordered dest col]
__device__ float g_W3J[HID * HID];
__device__ int g_u2[HID];           // col -> dest unit (layer 2 ordering)
__device__ int g_u3[HID];           // col -> dest unit (layer 3 ordering)
__device__ int g_S2[99];            // group prefix sums (98 groups)
__device__ int g_S3[2][50];         // per-parity group prefix sums
__device__ float g_fr[3];

// ---------------------------------------------------------------------------
__global__ void init_tables() {
    if (threadIdx.x != 0 || blockIdx.x != 0) return;
    int s = 0;
    for (int g = 0; g < 98; g++) {
        g_S2[g] = s;
        int rho = (3 * g) % 98;
        int cnt = (rho < 44) ? 11 : 10;
        for (int i = 0; i < cnt; i++) g_u2[s + i] = rho + 98 * i;
        s += cnt;
    }
    g_S2[98] = s;
    for (int p = 0; p < 2; p++) {
        int sp = 512 * p;
        for (int g3 = 0; g3 < 49; g3++) {
            g_S3[p][g3] = sp;
            int q = (2 * g3) % 49;
            int rho = 2 * q + p;
            int cnt = (rho < 44) ? 11 : 10;
            for (int i = 0; i < cnt; i++) g_u3[sp + i] = rho + 98 * i;
            sp += cnt;
        }
        g_S3[p][49] = sp;
    }
    g_fr[0] = 0.0f; g_fr[1] = 0.0f; g_fr[2] = 0.0f;
}

// ---------------------------------------------------------------------------
__global__ void prep_kernel(const float* __restrict__ W2,
                            const float* __restrict__ W3) {
    __shared__ float tile[32][33];
    __shared__ int uu[32];
    const float* src = (blockIdx.z == 0) ? W2 : W3;
    float* dst = (blockIdx.z == 0) ? g_W2J : g_W3J;
    const int* umap = (blockIdx.z == 0) ? g_u2 : g_u3;
    int c0 = blockIdx.x * 32, h0 = blockIdx.y * 32;
    int tx = threadIdx.x, ty = threadIdx.y;
    if (ty == 0) uu[tx] = umap[c0 + tx];
    __syncthreads();
    tile[ty][tx] = src[uu[ty] * HID + h0 + tx];
    __syncthreads();
    dst[(h0 + ty) * HID + c0 + tx] = tile[tx][ty];
}

// ---------------------------------------------------------------------------
static __device__ __forceinline__ unsigned long long addf32x2(
    unsigned long long a, unsigned long long b) {
    unsigned long long o;
    asm("add.rn.f32x2 %0, %1, %2;" : "=l"(o) : "l"(a), "l"(b));
    return o;
}

static __device__ __forceinline__ unsigned spread4(unsigned m) {
    return ((m & 0xFu) * 0x00204081u) & 0x01010101u;
}

static __device__ __forceinline__ unsigned bytesum(unsigned v, unsigned c) {
    unsigned ones = 0x01010101u;
    unsigned r;
    asm("dp4a.u32.u32 %0, %1, %2, %3;" : "=r"(r) : "r"(v), "r"(ones), "r"(c));
    return r;
}

// exclusive scan over 256 threads (8 warps)
static __device__ __forceinline__ void block_scan(int v, int tid, int* s_warp,
                                                  int& excl, int& total) {
    int lane = tid & 31, wid = tid >> 5;
    int x = v;
#pragma unroll
    for (int o = 1; o < 32; o <<= 1) {
        int y = __shfl_up_sync(0xffffffffu, x, o);
        if (lane >= o) x += y;
    }
    __syncthreads();
    if (lane == 31) s_warp[wid] = x;
    __syncthreads();
    int pre = 0, tot = 0;
#pragma unroll
    for (int w = 0; w < 8; w++) {
        int sw = s_warp[w];
        pre += (w < wid) ? sw : 0;
        tot += sw;
    }
    excl = pre + x - v;
    total = tot;
}

union F2U { unsigned long long u; float2 f; };

// one row: 4 mask tests (G=4), predicated packed adds into active pair accs
#define ACCR(e, v1, v2)                                                     \
    do {                                                                    \
        unsigned _m = (e) >> 10;                                            \
        if (_m & 1u) { if (A1) acc1[0] = addf32x2(acc1[0], (v1));           \
                       if (A2) acc2[0] = addf32x2(acc2[0], (v2)); }         \
        if (_m & 2u) { if (A1) acc1[1] = addf32x2(acc1[1], (v1));           \
                       if (A2) acc2[1] = addf32x2(acc2[1], (v2)); }         \
        if (_m & 4u) { if (A1) acc1[2] = addf32x2(acc1[2], (v1));           \
                       if (A2) acc2[2] = addf32x2(acc2[2], (v2)); }         \
        if (_m & 8u) { if (A1) acc1[3] = addf32x2(acc1[3], (v1));           \
                       if (A2) acc2[3] = addf32x2(acc2[3], (v2)); }         \
    } while (0)

// union-row gather, pair columns, depth-4 weight pipeline, compile-time pair
// activity (A1: cols 2tid..2tid+1 via pA; A2: +512 via pB)
template <bool A1, bool A2>
static __device__ __forceinline__ void gather_impl(
    const unsigned* __restrict__ list, int cnt,
    const unsigned long long* __restrict__ pA,
    const unsigned long long* __restrict__ pB,
    unsigned long long* acc1, unsigned long long* acc2) {
    const int nb = cnt >> 2;
    if (nb > 0) {
        uint4 c = *reinterpret_cast<const uint4*>(list);
        unsigned e0 = c.x, e1 = c.y, e2 = c.z, e3 = c.w;
        unsigned long long w10 = 0, w11 = 0, w12 = 0, w13 = 0;
        unsigned long long w20 = 0, w21 = 0, w22 = 0, w23 = 0;
        if (A1) {
            w10 = __ldg(pA + ((e0 & 1023u) << 9));
            w11 = __ldg(pA + ((e1 & 1023u) << 9));
            w12 = __ldg(pA + ((e2 & 1023u) << 9));
            w13 = __ldg(pA + ((e3 & 1023u) << 9));
        }
        if (A2) {
            w20 = __ldg(pB + ((e0 & 1023u) << 9));
            w21 = __ldg(pB + ((e1 & 1023u) << 9));
            w22 = __ldg(pB + ((e2 & 1023u) << 9));
            w23 = __ldg(pB + ((e3 & 1023u) << 9));
        }
        for (int b = 0; b < nb; b++) {
            unsigned f0 = e0, f1 = e1, f2 = e2, f3 = e3;
            unsigned long long v10 = w10, v11 = w11, v12 = w12, v13 = w13;
            unsigned long long v20 = w20, v21 = w21, v22 = w22, v23 = w23;
            if (b + 1 < nb) {
                uint4 n = *reinterpret_cast<const uint4*>(list + 4 * (b + 1));
                e0 = n.x; e1 = n.y; e2 = n.z; e3 = n.w;
                if (A1) {
                    w10 = __ldg(pA + ((e0 & 1023u) << 9));
                    w11 = __ldg(pA + ((e1 & 1023u) << 9));
                    w12 = __ldg(pA + ((e2 & 1023u) << 9));
                    w13 = __ldg(pA + ((e3 & 1023u) << 9));
                }
                if (A2) {
                    w20 = __ldg(pB + ((e0 & 1023u) << 9));
                    w21 = __ldg(pB + ((e1 & 1023u) << 9));
                    w22 = __ldg(pB + ((e2 & 1023u) << 9));
                    w23 = __ldg(pB + ((e3 & 1023u) << 9));
                }
            }
            ACCR(f0, v10, v20);
            ACCR(f1, v11, v21);
            ACCR(f2, v12, v22);
            ACCR(f3, v13, v23);
        }
    }
    for (int i = nb << 2; i < cnt; i++) {
        unsigned e = list[i];
        unsigned long long v1 = A1 ? __ldg(pA + ((e & 1023u) << 9)) : 0ull;
        unsigned long long v2 = A2 ? __ldg(pB + ((e & 1023u) << 9)) : 0ull;
        ACCR(e, v1, v2);
    }
}

static __device__ __forceinline__ void gatherP(
    const unsigned* __restrict__ list, int cnt,
    const unsigned long long* __restrict__ pA,
    const unsigned long long* __restrict__ pB, bool a1, bool a2,
    unsigned long long* acc1, unsigned long long* acc2) {
    if (cnt <= 0) return;
    if (a1) {
        if (a2) gather_impl<true, true>(list, cnt, pA, pB, acc1, acc2);
        else gather_impl<true, false>(list, cnt, pA, pB, acc1, acc2);
    } else if (a2) {
        gather_impl<false, true>(list, cnt, pA, pB, acc1, acc2);
    }
}

// ---------------------------------------------------------------------------
__global__ void __launch_bounds__(NTHR, 2) snn_kernel(
    const float* __restrict__ input,
    const float* __restrict__ W1, const float* __restrict__ b1,
    const float* __restrict__ b2, const float* __restrict__ b3,
    const float* __restrict__ W4, const float* __restrict__ b4,
    float* __restrict__ out) {
    __shared__ __align__(16) unsigned listA[512];
    __shared__ __align__(16) unsigned listB[1024];
    __shared__ int s_warp[8];
    __shared__ float xsh[G * 8];
    __shared__ float4 s_red4[8];
    __shared__ __align__(16) ulonglong2 dcsh[G * NTHR];  // const L1 drive

    const int tid = threadIdx.x;
    const int n0 = blockIdx.x * G;
    const int h0 = 4 * tid;  // layer-1 units

    // col maps: slot k -> col c = 512*(k>>1) + 2*tid + (k&1)
    int h2s[4], h3s[4];
    float b2v[4], b3v[4];
#pragma unroll
    for (int k = 0; k < 4; k++) {
        int c = 512 * (k >> 1) + 2 * tid + (k & 1);
        h2s[k] = __ldg(&g_u2[c]);
        h3s[k] = __ldg(&g_u3[c]);
        b2v[k] = __ldg(b2 + h2s[k]);
        b3v[k] = __ldg(b3 + h3s[k]);
    }
    unsigned long long bp2L, bp2H, bp3L, bp3H;
    {
        F2U a, b, c, d;
        a.f = make_float2(b2v[0], b2v[1]); bp2L = a.u;
        b.f = make_float2(b2v[2], b2v[3]); bp2H = b.u;
        c.f = make_float2(b3v[0], b3v[1]); bp3L = c.u;
        d.f = make_float2(b3v[2], b3v[3]); bp3H = d.u;
    }

    float m1[4][G], m2[4][G], m3[4][G];
#pragma unroll
    for (int k = 0; k < 4; k++)
#pragma unroll
        for (int g = 0; g < G; g++) {
            m1[k][g] = 0.f; m2[k][g] = 0.f; m3[k][g] = 0.f;
        }
    unsigned ss1[4] = {0,0,0,0}, ss2[4] = {0,0,0,0}, ss3[4] = {0,0,0,0};

    const float4* W14 = reinterpret_cast<const float4*>(W1);
    const unsigned long long* pA2 =
        reinterpret_cast<const unsigned long long*>(g_W2J) + tid;
    const unsigned long long* pB2 = pA2 + 256;
    const unsigned long long* pA3 =
        reinterpret_cast<const unsigned long long*>(g_W3J) + tid;
    const unsigned long long* pB3 = pA3 + 256;
    const int ra = 64 * (tid >> 5);  // warp region start (pair1 cols)

    // constant layer-1 drive (t >= 12 uses input slice at 776)
    if (tid < G * 8)
        xsh[tid] = __ldg(input + (n0 + (tid >> 3)) * 784 + 776 + (tid & 7));
    __syncthreads();
    {
        float4 bq1 = __ldg(reinterpret_cast<const float4*>(b1) + tid);
        float w1r[4][8];
#pragma unroll
        for (int k = 0; k < 4; k++) {
            float4 a = __ldg(W14 + (h0 + k) * 2);
            float4 c = __ldg(W14 + (h0 + k) * 2 + 1);
            w1r[k][0] = a.x; w1r[k][1] = a.y; w1r[k][2] = a.z; w1r[k][3] = a.w;
            w1r[k][4] = c.x; w1r[k][5] = c.y; w1r[k][6] = c.z; w1r[k][7] = c.w;
        }
        float bb[4] = {bq1.x, bq1.y, bq1.z, bq1.w};
#pragma unroll
        for (int g = 0; g < G; g++) {
            const float* x = &xsh[g * 8];
            float s[4];
#pragma unroll
            for (int k = 0; k < 4; k++) {
                float acc = bb[k];
#pragma unroll
                for (int i = 0; i < 8; i++) acc += x[i] * w1r[k][i];
                s[k] = acc;
            }
            F2U lo, hi;
            lo.f = make_float2(s[0], s[1]);
            hi.f = make_float2(s[2], s[3]);
            dcsh[g * NTHR + tid] = make_ulonglong2(lo.u, hi.u);
        }
    }
    __syncthreads();

    int w0 = 66;    // (33*t + 66) % 98 at t=0
    int g3lo = 25;  // (25*tau + 25) % 49 at tau=0

    for (int t = 0; t < TSTEPS; t++) {
        const int par = t & 1;

        // ---------- layer 1 drive ----------
        unsigned long long d1L[G], d1H[G];
        if (t < 12) {
            if (tid < G * 8)
                xsh[tid] =
                    __ldg(input + (n0 + (tid >> 3)) * 784 + t * 8 + (tid & 7));
            __syncthreads();
            float4 bq1 = __ldg(reinterpret_cast<const float4*>(b1) + tid);
            float w1r[4][8];
#pragma unroll
            for (int k = 0; k < 4; k++) {
                float4 a = __ldg(W14 + (h0 + k) * 2);
                float4 c = __ldg(W14 + (h0 + k) * 2 + 1);
                w1r[k][0] = a.x; w1r[k][1] = a.y; w1r[k][2] = a.z; w1r[k][3] = a.w;
                w1r[k][4] = c.x; w1r[k][5] = c.y; w1r[k][6] = c.z; w1r[k][7] = c.w;
            }
            float bb[4] = {bq1.x, bq1.y, bq1.z, bq1.w};
#pragma unroll
            for (int g = 0; g < G; g++) {
                const float* x = &xsh[g * 8];
                float s[4];
#pragma unroll
                for (int k = 0; k < 4; k++) {
                    float acc = bb[k];
#pragma unroll
                    for (int i = 0; i < 8; i++) acc += x[i] * w1r[k][i];
                    s[k] = acc;
                }
                F2U lo, hi;
                lo.f = make_float2(s[0], s[1]);
                hi.f = make_float2(s[2], s[3]);
                d1L[g] = lo.u;
                d1H[g] = hi.u;
            }
            __syncthreads();
        } else {
#pragma unroll
            for (int g = 0; g < G; g++) {
                ulonglong2 v = dcsh[g * NTHR + tid];
                d1L[g] = v.x;
                d1H[g] = v.y;
            }
        }

        // ---------- layer 1 update (eligible k = par, par+2) ----------
        unsigned mk0 = 0, mk2 = 0;
        if (par == 0) {
#pragma unroll
            for (int g = 0; g < G; g++) {
                F2U uL, uH; uL.u = d1L[g]; uH.u = d1H[g];
                float na = m1[0][g] * 0.5f + uL.f.x;
                float nc = m1[2][g] * 0.5f + uH.f.x;
                m1[0][g] = na; m1[2][g] = nc;
                if (na > 0.5f) mk0 |= 1u << g;
                if (nc > 0.5f) mk2 |= 1u << g;
            }
            ss1[0] += spread4(mk0);
            ss1[2] += spread4(mk2);
        } else {
#pragma unroll
            for (int g = 0; g < G; g++) {
                F2U uL, uH; uL.u = d1L[g]; uH.u = d1H[g];
                float na = m1[1][g] * 0.5f + uL.f.y;
                float nc = m1[3][g] * 0.5f + uH.f.y;
                m1[1][g] = na; m1[3][g] = nc;
                if (na > 0.5f) mk0 |= 1u << g;
                if (nc > 0.5f) mk2 |= 1u << g;
            }
            ss1[1] += spread4(mk0);
            ss1[3] += spread4(mk2);
        }

        int excl, cnt;
        block_scan((mk0 ? 1 : 0) + (mk2 ? 1 : 0), tid, s_warp, excl, cnt);
        {
            int p = excl;
            if (mk0) listA[p++] = (mk0 << 10) | (unsigned)(h0 + par);
            if (mk2) listA[p] = (mk2 << 10) | (unsigned)(h0 + par + 2);
        }
        __syncthreads();

        // ---------- layer 2: region gather + update ----------
        {
            int lo = __ldg(&g_S2[w0]);
            int hiI = w0 + 33;
            bool wrap = hiI > 98;
            int hi = wrap ? __ldg(&g_S2[hiI - 98]) : __ldg(&g_S2[hiI]);
            bool a1 = wrap ? (ra < hi || ra + 64 > lo)
                           : (ra + 64 > lo && ra < hi);
            int rb = 512 + ra;
            bool a2 = wrap ? (rb < hi || rb + 64 > lo)
                           : (rb + 64 > lo && rb < hi);
            unsigned long long acc1[G], acc2[G];
#pragma unroll
            for (int g = 0; g < G; g++) { acc1[g] = bp2L; acc2[g] = bp2H; }
            gatherP(listA, cnt, pA2, pB2, a1, a2, acc1, acc2);

            unsigned msk[4];
            int cl = 0;
#pragma unroll
            for (int k = 0; k < 4; k++) {
                int c = 512 * (k >> 1) + 2 * tid + (k & 1);
                bool el = wrap ? (c >= lo || c < hi) : (c >= lo && c < hi);
                msk[k] = 0;
                if (el) {
                    unsigned mm = 0;
#pragma unroll
                    for (int g = 0; g < G; g++) {
                        F2U u;
                        u.u = (k >> 1) ? acc2[g] : acc1[g];
                        float d = (k & 1) ? u.f.y : u.f.x;
                        float nm = m2[k][g] * 0.5f + d;
                        m2[k][g] = nm;
                        if (nm > 0.5f) mm |= 1u << g;
                    }
                    msk[k] = mm;
                    ss2[k] += spread4(mm);
                    cl += (mm ? 1 : 0);
                }
            }
            block_scan(cl, tid, s_warp, excl, cnt);
            {
                int p = excl;
#pragma unroll
                for (int k = 0; k < 4; k++)
                    if (msk[k]) listB[p++] = (msk[k] << 10) | (unsigned)h2s[k];
            }
            __syncthreads();
        }

        // ---------- layer 3: region gather + update ----------
        {
            int lo = __ldg(&g_S3[par][g3lo]);
            int hiI = g3lo + 25;
            bool wrap = hiI > 49;
            int hi = wrap ? __ldg(&g_S3[par][hiI - 49]) : __ldg(&g_S3[par][hiI]);
            int r1 = ra, r2 = 512 + ra;
            bool a1 = (par == 0) && (wrap ? (r1 < hi || r1 + 64 > lo)
                                          : (r1 + 64 > lo && r1 < hi));
            bool a2 = (par == 1) && (wrap ? (r2 < hi || r2 + 64 > lo)
                                          : (r2 + 64 > lo && r2 < hi));
            unsigned long long acc1[G], acc2[G];
#pragma unroll
            for (int g = 0; g < G; g++) { acc1[g] = bp3L; acc2[g] = bp3H; }
            gatherP(listB, cnt, pA3, pB3, a1, a2, acc1, acc2);

#pragma unroll
            for (int k = 0; k < 4; k++) {
                int p = k >> 1;
                int c = 512 * p + 2 * tid + (k & 1);
                bool el = (p == par) &&
                          (wrap ? (c >= lo || c < hi) : (c >= lo && c < hi));
                if (el) {
                    unsigned mm = 0;
#pragma unroll
                    for (int g = 0; g < G; g++) {
                        F2U u;
                        u.u = p ? acc2[g] : acc1[g];
                        float d = (k & 1) ? u.f.y : u.f.x;
                        float nm = m3[k][g] * 0.5f + d;
                        m3[k][g] = nm;
                        if (nm > 0.5f) mm |= 1u << g;
                    }
                    ss3[k] += spread4(mm);
                }
            }
        }

        // advance windows
        w0 += 33; if (w0 >= 98) w0 -= 98;
        if (par == 1) { g3lo += 25; if (g3lo >= 49) g3lo -= 49; }
    }

    // ------------------------- epilogue -------------------------
    const float inv = 1.0f / 98.0f;

#pragma unroll
    for (int g = 0; g < G; g++) {
        int sh = 8 * g;
        float4 v1 = make_float4((float)((ss1[0] >> sh) & 255u) * inv,
                                (float)((ss1[1] >> sh) & 255u) * inv,
                                (float)((ss1[2] >> sh) & 255u) * inv,
                                (float)((ss1[3] >> sh) & 255u) * inv);
        *reinterpret_cast<float4*>(out + 10240 + (n0 + g) * HID + h0) = v1;
    }
#pragma unroll
    for (int k = 0; k < 4; k++) {
#pragma unroll
        for (int g = 0; g < G; g++) {
            int sh = 8 * g;
            float a2 = (float)((ss2[k] >> sh) & 255u);
            float a3 = (float)((ss3[k] >> sh) & 255u);
            out[10240 + 1048576 + (n0 + g) * HID + h2s[k]] = a2 * inv;
            out[10240 + 2097152 + (n0 + g) * HID + h3s[k]] = a3 * inv;
        }
    }

    float s3f[4][G];
#pragma unroll
    for (int k = 0; k < 4; k++)
#pragma unroll
        for (int g = 0; g < G; g++)
            s3f[k][g] = (float)((ss3[k] >> (8 * g)) & 255u);

    const int lane = tid & 31, wid = tid >> 5;

    for (int o = 0; o < 10; o++) {
        float w4s[4];
#pragma unroll
        for (int k = 0; k < 4; k++) w4s[k] = __ldg(W4 + o * HID + h3s[k]);
        float4 v;
        v.x = s3f[0][0] * w4s[0] + s3f[1][0] * w4s[1] +
              s3f[2][0] * w4s[2] + s3f[3][0] * w4s[3];
        v.y = s3f[0][1] * w4s[0] + s3f[1][1] * w4s[1] +
              s3f[2][1] * w4s[2] + s3f[3][1] * w4s[3];
        v.z = s3f[0][2] * w4s[0] + s3f[1][2] * w4s[1] +
              s3f[2][2] * w4s[2] + s3f[3][2] * w4s[3];
        v.w = s3f[0][3] * w4s[0] + s3f[1][3] * w4s[1] +
              s3f[2][3] * w4s[2] + s3f[3][3] * w4s[3];
#pragma unroll
        for (int off = 16; off > 0; off >>= 1) {
            v.x += __shfl_down_sync(0xffffffffu, v.x, off);
            v.y += __shfl_down_sync(0xffffffffu, v.y, off);
            v.z += __shfl_down_sync(0xffffffffu, v.z, off);
            v.w += __shfl_down_sync(0xffffffffu, v.w, off);
        }
        if (lane == 0) s_red4[wid] = v;
        __syncthreads();
        if (tid == 0) {
            float4 s = make_float4(0, 0, 0, 0);
#pragma unroll
            for (int w = 0; w < 8; w++) {
                s.x += s_red4[w].x; s.y += s_red4[w].y;
                s.z += s_red4[w].z; s.w += s_red4[w].w;
            }
            float bo = __ldg(b4 + o);
            out[(n0 + 0) * 10 + o] = s.x / 98.0f + bo;
            out[(n0 + 1) * 10 + o] = s.y / 98.0f + bo;
            out[(n0 + 2) * 10 + o] = s.z / 98.0f + bo;
            out[(n0 + 3) * 10 + o] = s.w / 98.0f + bo;
        }
        __syncthreads();
    }

    unsigned c1 = 0, c2 = 0, c3 = 0;
#pragma unroll
    for (int k = 0; k < 4; k++) {
        c1 = bytesum(ss1[k], c1);
        c2 = bytesum(ss2[k], c2);
        c3 = bytesum(ss3[k], c3);
    }
    {
        float4 v = make_float4((float)c1, (float)c2, (float)c3, 0.0f);
#pragma unroll
        for (int off = 16; off > 0; off >>= 1) {
            v.x += __shfl_down_sync(0xffffffffu, v.x, off);
            v.y += __shfl_down_sync(0xffffffffu, v.y, off);
            v.z += __shfl_down_sync(0xffffffffu, v.z, off);
        }
        if (lane == 0) s_red4[wid] = v;
        __syncthreads();
        if (tid == 0) {
            float s0 = 0, s1 = 0, s2 = 0;
#pragma unroll
            for (int w = 0; w < 8; w++) {
                s0 += s_red4[w].x; s1 += s_red4[w].y; s2 += s_red4[w].z;
            }
            atomicAdd(&g_fr[0], s0);
            atomicAdd(&g_fr[1], s1);
            atomicAdd(&g_fr[2], s2);
        }
    }
}

__global__ void finalize_kernel(float* __restrict__ out) {
    if (threadIdx.x < 3)
        out[3155968 + threadIdx.x] = g_fr[threadIdx.x] / 102760448.0f;
}

extern "C" void kernel_launch(void* const* d_in, const int* in_sizes, int n_in,
                              void* d_out, int out_size) {
    const float* input = (const float*)d_in[0];
    const float* W1 = (const float*)d_in[1];
    const float* b1 = (const float*)d_in[2];
    const float* W2 = (const float*)d_in[3];
    const float* b2 = (const float*)d_in[4];
    const float* W3 = (const float*)d_in[5];
    const float* b3 = (const float*)d_in[6];
    const float* W4 = (const float*)d_in[7];
    const float* b4 = (const float*)d_in[8];
    (void)in_sizes; (void)n_in; (void)out_size;

    init_tables<<<1, 1>>>();
    dim3 pgrid(HID / 32, HID / 32, 2);
    prep_kernel<<<pgrid, dim3(32, 32)>>>(W2, W3);
    snn_kernel<<<NCTA, NTHR>>>(input, W1, b1, b2, b3, W4, b4, (float*)d_out);
    finalize_kernel<<<1, 32>>>((float*)d_out);
}